// round 8
// baseline (speedup 1.0000x reference)
#include <cuda_runtime.h>
#include <cuda_bf16.h>

// Problem constants (fixed by the reference)
#define BB  4
#define LL  512
#define HH  768
#define SS  100
#define RR  100
#define EE  25
#define NEC 10              // entity classes
#define NRC 6               // relation classes
#define NEGV (-1e20f)

#define H4       (HH/4)         // 192 float4 lanes per hidden row
#define SPAN_DIM (HH + EE)      // 793
#define SPAN_PAD 800            // padded (mult of 4), zero tail
#define NENT     (BB*SS)        // 400
#define NREL     (BB*RR)        // 400
#define NROW     (NEC + 2*NRC)  // 22 projection rows per entity

// Scratch (static device globals — no runtime allocation)
// wentT rows: [0,10) = w_span^T ; [10,16) = head-slice^T ; [16,22) = tail-slice^T
// (head slice = w_rel rows 768..1536 ++ 2304..2329 ; tail = 1536..2304 ++ 2329..2354)
__device__ float g_wentT[NROW*SPAN_PAD];   // 22 x 800
__device__ float g_wctxT[NRC*HH];          // 6 x 768 (w_rel rows 0..768 transposed)
__device__ float g_p1[NENT*NRC];           // head projections per entity
__device__ float g_p2[NENT*NRC];           // tail projections per entity
__device__ float g_pc[NREL*NRC];           // ctx projections per relation

// -----------------------------------------------------------------------------
// A0: transpose weights into coalesce-friendly padded layouts (runs first)
// -----------------------------------------------------------------------------
__global__ void __launch_bounds__(256)
spert_wtrans_kernel(const float* __restrict__ w_span,
                    const float* __restrict__ w_rel)
{
    const int i = blockIdx.x * 256 + threadIdx.x;
    if (i < NROW*SPAN_PAD) {
        const int row = i / SPAN_PAD, k = i - row*SPAN_PAD;
        float v = 0.f;
        if (row < NEC) {
            if (k < SPAN_DIM) v = w_span[k*NEC + row];
        } else if (row < NEC + NRC) {
            const int j = row - NEC;
            if      (k < HH)       v = w_rel[(HH + k)*NRC + j];
            else if (k < SPAN_DIM) v = w_rel[(3*HH + (k - HH))*NRC + j];
        } else {
            const int j = row - NEC - NRC;
            if      (k < HH)       v = w_rel[(2*HH + k)*NRC + j];
            else if (k < SPAN_DIM) v = w_rel[(3*HH + EE + (k - HH))*NRC + j];
        }
        g_wentT[i] = v;
    } else {
        const int i2 = i - NROW*SPAN_PAD;
        if (i2 < NRC*HH) {
            const int j = i2 / HH, k = i2 - j*HH;
            g_wctxT[i2] = w_rel[k*NRC + j];
        }
    }
}
#define A0_GRID ((NROW*SPAN_PAD + NRC*HH + 255) / 256)   // 87

// -----------------------------------------------------------------------------
// A: pooling + in-register projections.
//   blocks [0,400):   entity — pool span, 22 dots -> entity logits + p1/p2
//   blocks [400,800): ctx    — pool span, 6 dots  -> pc
// Pooled repr never leaves registers; weights read as coalesced LDG.128
// from transposed scratch (L1-resident across blocks on an SM).
// -----------------------------------------------------------------------------
__global__ void __launch_bounds__(256)
spert_pool_proj_kernel(const float* __restrict__ hid,
                       const int*   __restrict__ emask,
                       const int*   __restrict__ cmask,
                       const float* __restrict__ size_emb,
                       const float* __restrict__ b_span,
                       float*       __restrict__ out)
{
    __shared__ float sred[8][NROW];
    __shared__ int s_start;

    const int bid = blockIdx.x;
    const int t   = threadIdx.x;
    const bool is_ent = (bid < NENT);
    const int idx  = is_ent ? bid : bid - NENT;   // b*N + n
    const int b    = idx / SS;
    const int lane = t & 31, warp = t >> 5;

    // ---- recover contiguous span (start, len): ballot min + syncthreads_count ----
    const int* mrow = (is_ent ? emask : cmask) + (size_t)idx * LL;
    const int m0 = mrow[t];
    const int m1 = mrow[t + 256];
    if (t == 0) s_start = LL;
    __syncthreads();
    unsigned bal0 = __ballot_sync(0xffffffffu, m0 != 0);
    unsigned bal1 = __ballot_sync(0xffffffffu, m1 != 0);
    if (lane == 0) {
        if (bal0) atomicMin(&s_start, (warp << 5) + __ffs(bal0) - 1);
        if (bal1) atomicMin(&s_start, 256 + (warp << 5) + __ffs(bal1) - 1);
    }
    const int len = __syncthreads_count(m0 != 0) + __syncthreads_count(m1 != 0);
    const int start = s_start;   // barrier above orders the atomics

    // ---- masked max pool over span (float4, unroll 8 for MLP) ----
    float4 rv = make_float4(0.f, 0.f, 0.f, 0.f);   // this thread's repr chunk
    if (t < H4) {
        float4 mx = make_float4(NEGV, NEGV, NEGV, NEGV);
        const float4* hb = reinterpret_cast<const float4*>(hid + (size_t)b * LL * HH) + t;
        int l = start;
        const int e = start + len;
        for (; l + 8 <= e; l += 8) {
            float4 v0 = hb[(size_t)(l+0) * H4];
            float4 v1 = hb[(size_t)(l+1) * H4];
            float4 v2 = hb[(size_t)(l+2) * H4];
            float4 v3 = hb[(size_t)(l+3) * H4];
            float4 v4 = hb[(size_t)(l+4) * H4];
            float4 v5 = hb[(size_t)(l+5) * H4];
            float4 v6 = hb[(size_t)(l+6) * H4];
            float4 v7 = hb[(size_t)(l+7) * H4];
            mx.x = fmaxf(mx.x, fmaxf(fmaxf(fmaxf(v0.x, v1.x), fmaxf(v2.x, v3.x)),
                                     fmaxf(fmaxf(v4.x, v5.x), fmaxf(v6.x, v7.x))));
            mx.y = fmaxf(mx.y, fmaxf(fmaxf(fmaxf(v0.y, v1.y), fmaxf(v2.y, v3.y)),
                                     fmaxf(fmaxf(v4.y, v5.y), fmaxf(v6.y, v7.y))));
            mx.z = fmaxf(mx.z, fmaxf(fmaxf(fmaxf(v0.z, v1.z), fmaxf(v2.z, v3.z)),
                                     fmaxf(fmaxf(v4.z, v5.z), fmaxf(v6.z, v7.z))));
            mx.w = fmaxf(mx.w, fmaxf(fmaxf(fmaxf(v0.w, v1.w), fmaxf(v2.w, v3.w)),
                                     fmaxf(fmaxf(v4.w, v5.w), fmaxf(v6.w, v7.w))));
        }
        for (; l < e; ++l) {
            float4 v = hb[(size_t)l * H4];
            mx.x = fmaxf(mx.x, v.x); mx.y = fmaxf(mx.y, v.y);
            mx.z = fmaxf(mx.z, v.z); mx.w = fmaxf(mx.w, v.w);
        }
        rv = mx;
    }

    if (is_ent) {
        // threads [192,200) own the size-embedding dims (k = 768..799, zero-padded)
        if (t >= H4 && t < SPAN_PAD/4) {
            const int k = 4*t - HH;          // 0,4,...,28
            const float* se = size_emb + len*EE;
            rv.x = (k+0 < EE) ? se[k+0] : 0.f;
            rv.y = (k+1 < EE) ? se[k+1] : 0.f;
            rv.z = (k+2 < EE) ? se[k+2] : 0.f;
            rv.w = (k+3 < EE) ? se[k+3] : 0.f;
        }

        // 22 dots: repr(this thread's 4 dims) x wentT rows, coalesced LDG.128
        float acc[NROW];
        #pragma unroll
        for (int r = 0; r < NROW; ++r) acc[r] = 0.f;
        if (t < SPAN_PAD/4) {
            const float* wb = g_wentT + 4*t;
            #pragma unroll
            for (int r = 0; r < NROW; ++r) {
                float4 w = *reinterpret_cast<const float4*>(wb + r*SPAN_PAD);
                acc[r] = rv.x*w.x + rv.y*w.y + rv.z*w.z + rv.w*w.w;
            }
        }
        #pragma unroll
        for (int r = 0; r < NROW; ++r) {
            float v = acc[r];
            #pragma unroll
            for (int o = 16; o; o >>= 1) v += __shfl_down_sync(0xffffffffu, v, o);
            if (lane == 0) sred[warp][r] = v;
        }
        __syncthreads();
        if (t < NROW) {
            float s = 0.f;
            #pragma unroll
            for (int w = 0; w < 8; ++w) s += sred[w][t];
            if      (t < NEC)       out[idx*NEC + t]            = s + b_span[t];
            else if (t < NEC + NRC) g_p1[idx*NRC + (t - NEC)]       = s;
            else                    g_p2[idx*NRC + (t - NEC - NRC)] = s;
        }
    } else {
        // ctx block: 6 dots vs wctxT (768 dims, threads < 192 active)
        float acc[NRC];
        #pragma unroll
        for (int r = 0; r < NRC; ++r) acc[r] = 0.f;
        if (t < H4) {
            const float* wb = g_wctxT + 4*t;
            #pragma unroll
            for (int r = 0; r < NRC; ++r) {
                float4 w = *reinterpret_cast<const float4*>(wb + r*HH);
                acc[r] = rv.x*w.x + rv.y*w.y + rv.z*w.z + rv.w*w.w;
            }
        }
        #pragma unroll
        for (int r = 0; r < NRC; ++r) {
            float v = acc[r];
            #pragma unroll
            for (int o = 16; o; o >>= 1) v += __shfl_down_sync(0xffffffffu, v, o);
            if (lane == 0) sred[warp][r] = v;
        }
        __syncthreads();
        if (t < NRC) {
            float s = 0.f;
            #pragma unroll
            for (int w = 0; w < 8; ++w) s += sred[w][t];
            g_pc[idx*NRC + t] = s;
        }
    }
}

// -----------------------------------------------------------------------------
// B: trivial gather-add: rel_logits = pc + p1[head] + p2[tail] + bias
// -----------------------------------------------------------------------------
__global__ void __launch_bounds__(256)
spert_combine_kernel(const int*   __restrict__ rel,
                     const float* __restrict__ b_rel,
                     float*       __restrict__ out)
{
    const int i = blockIdx.x * 256 + threadIdx.x;
    if (i < NREL*NRC) {
        const int rid = i / NRC, j = i - rid*NRC;
        const int b   = rid / RR;
        const int hi  = rel[rid*2 + 0];
        const int ti  = rel[rid*2 + 1];
        out[NENT*NEC + i] = g_pc[i]
                          + g_p1[(b*SS + hi)*NRC + j]
                          + g_p2[(b*SS + ti)*NRC + j]
                          + b_rel[j];
    }
}

// -----------------------------------------------------------------------------
// kernel_launch: inputs per metadata order:
//   0 hidden_states (f32)  1 entity_masks (i32)  2 relations (i32)
//   3 relation_context_masks (i32)  4 size_emb (f32)
//   5 w_span (f32)  6 b_span (f32)  7 w_rel (f32)  8 b_rel (f32)
// out: 6400 f32 = entity_logits (4000) ++ relation_logits (2400)
// -----------------------------------------------------------------------------
extern "C" void kernel_launch(void* const* d_in, const int* in_sizes, int n_in,
                              void* d_out, int out_size)
{
    const float* hid      = (const float*)d_in[0];
    const int*   emask    = (const int*)  d_in[1];
    const int*   rel      = (const int*)  d_in[2];
    const int*   cmask    = (const int*)  d_in[3];
    const float* size_emb = (const float*)d_in[4];
    const float* w_span   = (const float*)d_in[5];
    const float* b_span   = (const float*)d_in[6];
    const float* w_rel    = (const float*)d_in[7];
    const float* b_rel    = (const float*)d_in[8];
    float* out = (float*)d_out;

    spert_wtrans_kernel<<<A0_GRID, 256>>>(w_span, w_rel);
    spert_pool_proj_kernel<<<NENT + NREL, 256>>>(hid, emask, cmask, size_emb,
                                                 b_span, out);
    spert_combine_kernel<<<(NREL*NRC + 255)/256, 256>>>(rel, b_rel, out);
}